// round 12
// baseline (speedup 1.0000x reference)
#include <cuda_runtime.h>
#include <cuda_bf16.h>
#include <cooperative_groups.h>
#include <math.h>
#include <stdint.h>

namespace cg = cooperative_groups;

// ---------------------------------------------------------------------------
// ChainLoss (pychain leaky-HMM forward objective), den + num graphs.
//   1. k_exp: xexp = exp(clip(x)) once into a device-global.
//   2. Counting-sort edges into CSR by e_out (hist/scan/scatter); edges packed
//      to 8B {in | pdf<<16, prob}.
//   3. k_main: cluster-2 per (graph,batch). alpha fully local per CTA; each CTA
//      computes anew for half the output states (warp-per-state segment sums,
//      register-cached row bounds via shfl, coalesced edge loads, shfl reduce,
//      zero atomics), pushes the raw half + half-sum to its peer via DSMEM
//      (parity double-buffered), ONE cluster.sync per frame, then both CTAs
//      renorm the full alpha locally.
//   4. k_final combines to the scalar.
// ---------------------------------------------------------------------------

#define BB     32
#define DD     2048
#define TT_MAX 400
#define S_DEN  2000
#define E_DEN  60000
#define S_NUM  512
#define E_NUM  2048

#define DEN_LEAKY 1e-5f
#define NUM_LEAKY 1e-20f

// -------- static scratch (no allocations allowed) --------
__device__ float g_xexp[(size_t)BB * TT_MAX * DD];   // ~100 MB

__device__ int   g_den_hist[2048];
__device__ int   g_den_rowptr[S_DEN + 1];
__device__ int   g_den_cursor[S_DEN];
__device__ uint2 g_den_edges[E_DEN];

__device__ int   g_num_hist[BB * S_NUM];
__device__ int   g_num_rowptr[BB * (S_NUM + 1)];
__device__ int   g_num_cursor[BB * S_NUM];
__device__ uint2 g_num_edges[BB * E_NUM];

__device__ double g_partial[2 * BB];

// ---------------------------------------------------------------------------
__device__ __forceinline__ float warp_sum(float v) {
    v += __shfl_xor_sync(0xFFFFFFFFu, v, 16);
    v += __shfl_xor_sync(0xFFFFFFFFu, v, 8);
    v += __shfl_xor_sync(0xFFFFFFFFu, v, 4);
    v += __shfl_xor_sync(0xFFFFFFFFu, v, 2);
    v += __shfl_xor_sync(0xFFFFFFFFu, v, 1);
    return v;
}

// ---------------------------------------------------------------------------
__global__ void k_exp(const float* __restrict__ x, int n4) {
    int i = blockIdx.x * blockDim.x + threadIdx.x;
    if (i < n4) {
        float4 v = ((const float4*)x)[i];
        float4 o;
        o.x = __expf(fminf(fmaxf(v.x, -30.0f), 30.0f));
        o.y = __expf(fminf(fmaxf(v.y, -30.0f), 30.0f));
        o.z = __expf(fminf(fmaxf(v.z, -30.0f), 30.0f));
        o.w = __expf(fminf(fmaxf(v.w, -30.0f), 30.0f));
        ((float4*)g_xexp)[i] = o;
    }
}

__global__ void k_zero() {
    int i = blockIdx.x * blockDim.x + threadIdx.x;
    if (i < 2048) g_den_hist[i] = 0;
    if (i < BB * S_NUM) g_num_hist[i] = 0;
}

__global__ void k_hist(const int* __restrict__ den_out,
                       const int* __restrict__ num_out) {
    int i = blockIdx.x * blockDim.x + threadIdx.x;
    if (i < E_DEN) atomicAdd(&g_den_hist[den_out[i]], 1);
    if (i < BB * E_NUM) {
        int b = i / E_NUM;
        atomicAdd(&g_num_hist[b * S_NUM + num_out[i]], 1);
    }
}

// block 0: scan den hist (2048); blocks 1..BB: per-batch num scans (512)
__global__ void k_scan() {
    __shared__ int s[2048];
    int blk = blockIdx.x;
    int tid = threadIdx.x;  // blockDim = 1024
    if (blk == 0) {
        int i0 = tid, i1 = tid + 1024;
        s[i0] = g_den_hist[i0];
        s[i1] = g_den_hist[i1];
        __syncthreads();
        for (int off = 1; off < 2048; off <<= 1) {
            int t0 = (i0 >= off) ? s[i0 - off] : 0;
            int t1 = (i1 >= off) ? s[i1 - off] : 0;
            __syncthreads();
            s[i0] += t0;
            s[i1] += t1;
            __syncthreads();
        }
        if (i0 < S_DEN) {
            g_den_rowptr[i0 + 1] = s[i0];
            g_den_cursor[i0] = (i0 == 0) ? 0 : s[i0 - 1];
        }
        if (i1 < S_DEN) {
            g_den_rowptr[i1 + 1] = s[i1];
            g_den_cursor[i1] = s[i1 - 1];
        }
        if (tid == 0) g_den_rowptr[0] = 0;
    } else {
        int b = blk - 1;
        if (tid < S_NUM) s[tid] = g_num_hist[b * S_NUM + tid];
        __syncthreads();
        for (int off = 1; off < S_NUM; off <<= 1) {
            int t0 = (tid < S_NUM && tid >= off) ? s[tid - off] : 0;
            __syncthreads();
            if (tid < S_NUM) s[tid] += t0;
            __syncthreads();
        }
        if (tid < S_NUM) {
            g_num_rowptr[b * (S_NUM + 1) + tid + 1] = s[tid];
            g_num_cursor[b * S_NUM + tid] = (tid == 0) ? 0 : s[tid - 1];
        }
        if (tid == 0) g_num_rowptr[b * (S_NUM + 1)] = 0;
    }
}

__global__ void k_scatter(const int* __restrict__ den_in, const int* __restrict__ den_out,
                          const int* __restrict__ den_pdf, const float* __restrict__ den_prob,
                          const int* __restrict__ num_in, const int* __restrict__ num_out,
                          const int* __restrict__ num_pdf, const float* __restrict__ num_prob) {
    int i = blockIdx.x * blockDim.x + threadIdx.x;
    if (i < E_DEN) {
        int o = den_out[i];
        int pos = atomicAdd(&g_den_cursor[o], 1);
        g_den_edges[pos] = make_uint2((unsigned)den_in[i] | ((unsigned)den_pdf[i] << 16),
                                      __float_as_uint(den_prob[i]));
    }
    if (i < BB * E_NUM) {
        int b = i / E_NUM;
        int o = num_out[i];
        int pos = atomicAdd(&g_num_cursor[b * S_NUM + o], 1);
        g_num_edges[b * E_NUM + pos] =
            make_uint2((unsigned)num_in[i] | ((unsigned)num_pdf[i] << 16),
                       __float_as_uint(num_prob[i]));
    }
}

// ---------------------------------------------------------------------------
// Main recursion. grid = 128 CTAs, cluster 2. pair = blockIdx/2:
// pairs 0..31 den batches, 32..63 num batches. Each CTA computes anew for half
// the states; halves exchanged raw via DSMEM; ONE cluster.sync per frame.
// Row bounds live in registers (lane k of warp w holds bounds of state
// base + w + 32k), broadcast by shfl in the hot loop — no SMEM rp array.
// ---------------------------------------------------------------------------
__global__ void __cluster_dims__(2, 1, 1) __launch_bounds__(1024, 1)
k_main(const int* __restrict__ xlen,
       const float* __restrict__ den_leaky, const float* __restrict__ den_final,
       const float* __restrict__ num_leaky, const float* __restrict__ num_final,
       int Tdim) {
    __shared__ float xs[DD];                              //  8192 B
    __shared__ float alpha[S_DEN];                        //  8000 B (local only)
    __shared__ __align__(16) float anewbuf[2 * S_DEN];    // 16000 B (parity dbl buf)
    __shared__ float clk[S_DEN];                          //  8000 B (coeff * leaky)
    __shared__ float red[32];
    __shared__ __align__(8) float hsum_own[2];
    __shared__ __align__(8) float hsum_peer[2];

    cg::cluster_group cluster = cg::this_cluster();
    int rank = (int)cluster.block_rank();
    int peer = rank ^ 1;

    int bid = blockIdx.x;
    int pair = bid >> 1;
    int b = pair & 31;
    bool isDen = pair < 32;

    int S = isDen ? S_DEN : S_NUM;
    int Shalf = S >> 1;
    int base = rank * Shalf;
    float coeff = isDen ? DEN_LEAKY : NUM_LEAKY;
    const uint2* __restrict__ edges = isDen ? g_den_edges : (g_num_edges + b * E_NUM);
    const int* rowptr = isDen ? g_den_rowptr : (g_num_rowptr + b * (S_NUM + 1));
    const float* leaky = isDen ? den_leaky : (num_leaky + b * S_NUM);
    const float* finalp = isDen ? den_final : (num_final + b * S_NUM);

    int tid = threadIdx.x;
    int wid = tid >> 5;
    int lane = tid & 31;

    for (int s = tid; s < S; s += 1024) {
        float cl = coeff * leaky[s];
        clk[s] = cl;
        alpha[s] = cl + (s == 0 ? 1.0f : 0.0f);
    }

    // register-cached row bounds: lane k holds bounds of state base + wid + 32k
    int nk = (Shalf - wid + 31) >> 5;       // warp-uniform trip count
    int re0 = 0, re1 = 0;
    {
        int sreg = base + wid + 32 * lane;
        if (lane < nk && sreg < base + Shalf) {
            re0 = rowptr[sreg];
            re1 = rowptr[sreg + 1];
        }
    }

    int Tb = xlen[b];
    const float* xb = g_xexp + (size_t)b * Tdim * DD;
    double logz = 0.0;

    // hoisted peer DSMEM pointers (map once, reuse every frame)
    uint64_t* peer_anew[2];
    float* peer_hsum_p;
    peer_anew[0] = (uint64_t*)cluster.map_shared_rank(anewbuf + base, peer);
    peer_anew[1] = (uint64_t*)cluster.map_shared_rank(anewbuf + S_DEN + base, peer);
    peer_hsum_p  = cluster.map_shared_rank(hsum_peer, peer);

    // preload frame 0 into registers
    float r0 = xb[tid], r1 = xb[tid + 1024];

    for (int t = 0; t < Tb; t++) {
        int par = t & 1;
        float* anew = anewbuf + par * S_DEN;

        // stage x row (prefetched previous iteration); this barrier also orders
        // init/renorm alpha writes before this frame's gathers
        xs[tid] = r0;
        xs[tid + 1024] = r1;
        __syncthreads();
        if (t + 1 < Tb) {
            const float* nx = xb + (size_t)(t + 1) * DD;
            r0 = nx[tid];
            r1 = nx[tid + 1024];
        }

        // phase 2: warp-per-state segment sums over own half (no atomics);
        // row bounds broadcast from registers (no crossbar traffic)
        float wsum = 0.0f;
        int s = base + wid;
        for (int k = 0; k < nk; k++, s += 32) {
            int e0 = __shfl_sync(0xFFFFFFFFu, re0, k);
            int e1 = __shfl_sync(0xFFFFFFFFu, re1, k);
            float acc = 0.0f;
            for (int e = e0 + lane; e < e1; e += 32) {
                uint2 ed = __ldg(&edges[e]);
                acc += alpha[ed.x & 0xFFFFu] * __uint_as_float(ed.y) * xs[ed.x >> 16];
            }
            acc = warp_sum(acc);
            if (lane == 0) anew[s] = acc;
            wsum += acc;  // identical in all lanes after butterfly
        }
        if (lane == 0) red[wid] = wsum;
        __syncthreads();  // anew own-half + red[] complete

        // half-sum: reduce + push to peer
        if (wid == 0) {
            float h = warp_sum(red[lane]);
            if (lane == 0) {
                hsum_own[par] = h;
                peer_hsum_p[par] = h;
            }
        }

        // push raw own half to peer's anew (packed 8B; 16B-aligned buffer)
        {
            const uint64_t* src = (const uint64_t*)(anew + base);
            uint64_t* dst = peer_anew[par];
            int n2 = Shalf >> 1;
            for (int i = tid; i < n2; i += 1024)
                dst[i] = src[i];
        }

        cluster.sync();  // single barrier: peer half + half-sum visible

        float asum = hsum_own[par] + hsum_peer[par];
        float inv = 1.0f / asum;

        // renorm + leaky over FULL state vector, locally
        for (int i = tid; i < S; i += 1024)
            alpha[i] = anew[i] * inv + clk[i];
        if (tid == 0) logz += (double)logf(asum);
        // no trailing barrier: next frame's post-staging __syncthreads orders
        // these alpha writes against the next gathers.
    }

    // final-state weighting (alpha fully local in both ranks; rank 0 reports)
    __syncthreads();
    if (rank == 0) {
        float p = 0.0f;
        for (int i = tid; i < S; i += 1024) p += alpha[i] * finalp[i];
        p = warp_sum(p);
        if (lane == 0) red[wid] = p;
        __syncthreads();
        if (wid == 0) {
            float v = warp_sum(red[lane]);
            if (lane == 0) g_partial[pair] = logz + (double)logf(v);
        }
    }
    cluster.sync();  // peer must not exit while pushes may be in flight
}

__global__ void k_final(const int* __restrict__ xlen, float* __restrict__ out) {
    int lane = threadIdx.x;  // 32 threads
    double dden = g_partial[lane];
    double dnum = g_partial[32 + lane];
    long long len = (long long)xlen[lane];
    for (int d = 16; d; d >>= 1) {
        dden += __shfl_xor_sync(0xFFFFFFFFu, dden, d);
        dnum += __shfl_xor_sync(0xFFFFFFFFu, dnum, d);
        len  += __shfl_xor_sync(0xFFFFFFFFu, len, d);
    }
    if (lane == 0) out[0] = (float)(-(dnum - dden) / (double)len);
}

// ---------------------------------------------------------------------------
extern "C" void kernel_launch(void* const* d_in, const int* in_sizes, int n_in,
                              void* d_out, int out_size) {
    const float* x         = (const float*)d_in[0];
    const int*   xlen      = (const int*)d_in[1];
    const int*   den_e_in  = (const int*)d_in[2];
    const int*   den_e_out = (const int*)d_in[3];
    const int*   den_e_pdf = (const int*)d_in[4];
    const float* den_e_prob= (const float*)d_in[5];
    const float* den_leaky = (const float*)d_in[6];
    const float* den_final = (const float*)d_in[7];
    const int*   num_e_in  = (const int*)d_in[8];
    const int*   num_e_out = (const int*)d_in[9];
    const int*   num_e_pdf = (const int*)d_in[10];
    const float* num_e_prob= (const float*)d_in[11];
    const float* num_leaky = (const float*)d_in[12];
    const float* num_final = (const float*)d_in[13];
    float* out = (float*)d_out;

    int Tdim = in_sizes[0] / (BB * DD);  // x = [B, T, D]
    int n4 = in_sizes[0] / 4;

    k_exp<<<(n4 + 255) / 256, 256>>>(x, n4);

    int zn = 2048 > BB * S_NUM ? 2048 : BB * S_NUM;
    k_zero<<<(zn + 255) / 256, 256>>>();

    int hn = E_DEN > BB * E_NUM ? E_DEN : BB * E_NUM;
    k_hist<<<(hn + 255) / 256, 256>>>(den_e_out, num_e_out);

    k_scan<<<1 + BB, 1024>>>();

    k_scatter<<<(hn + 255) / 256, 256>>>(den_e_in, den_e_out, den_e_pdf, den_e_prob,
                                         num_e_in, num_e_out, num_e_pdf, num_e_prob);

    k_main<<<4 * BB, 1024>>>(xlen, den_leaky, den_final, num_leaky, num_final, Tdim);

    k_final<<<1, 32>>>(xlen, out);
}

// round 14
// speedup vs baseline: 2.4727x; 2.4727x over previous
#include <cuda_runtime.h>
#include <cuda_bf16.h>
#include <cooperative_groups.h>
#include <math.h>
#include <stdint.h>

namespace cg = cooperative_groups;

// ---------------------------------------------------------------------------
// ChainLoss (pychain leaky-HMM forward objective), den + num graphs.
//   1. k_exp: xexp = exp(clip(x)) once into a device-global.
//   2. Edges repacked into SELL-32 (sliced-ELL): 32 states per slice, lane L
//      owns state 32*slice+L, edge slot j at slice_base + j*32 + L (coalesced,
//      zero-padded to the slice's max row length). No CSR, no scan.
//   3. k_main: cluster-2 per (graph,batch). One slice per warp: each lane
//      serially accumulates its state's row (independent coalesced LDGs,
//      register accumulator, ZERO per-state shfls), one warp-sum per warp for
//      asum. Halves exchanged raw via DSMEM (parity double-buffered), ONE
//      cluster.sync per frame, then both CTAs renorm the full alpha locally.
//   4. k_final combines to the scalar.
// ---------------------------------------------------------------------------

#define BB     32
#define DD     2048
#define S_DEN  2000
#define E_DEN  60000
#define S_NUM  512
#define E_NUM  2048

#define DEN_SLICES 63     // ceil(2000/32)
#define DEN_CAP    96     // max edges/row (Poisson(30), P(>=96) ~ 1e-21)
#define NUM_SLICES 16     // per batch: 512/32
#define NUM_CAP    32     // Poisson(4), P(>=32) ~ 1e-15

#define DEN_LEAKY 1e-5f
#define NUM_LEAKY 1e-20f

// -------- static scratch (no allocations allowed) --------
__device__ float g_xexp[(size_t)BB * 400 * DD];      // ~100 MB (T<=400)

__device__ uint2 g_den_sell[DEN_SLICES * DEN_CAP * 32];       // 1.5 MB
__device__ int   g_den_cnt[S_DEN];
__device__ int   g_den_slen[DEN_SLICES];

__device__ uint2 g_num_sell[BB * NUM_SLICES * NUM_CAP * 32];  // 4.2 MB
__device__ int   g_num_cnt[BB * S_NUM];
__device__ int   g_num_slen[BB * NUM_SLICES];

__device__ double g_partial[2 * BB];

// ---------------------------------------------------------------------------
__device__ __forceinline__ float warp_sum(float v) {
    v += __shfl_xor_sync(0xFFFFFFFFu, v, 16);
    v += __shfl_xor_sync(0xFFFFFFFFu, v, 8);
    v += __shfl_xor_sync(0xFFFFFFFFu, v, 4);
    v += __shfl_xor_sync(0xFFFFFFFFu, v, 2);
    v += __shfl_xor_sync(0xFFFFFFFFu, v, 1);
    return v;
}

// ---------------------------------------------------------------------------
__global__ void k_exp(const float* __restrict__ x, int n4) {
    int i = blockIdx.x * blockDim.x + threadIdx.x;
    if (i < n4) {
        float4 v = ((const float4*)x)[i];
        float4 o;
        o.x = __expf(fminf(fmaxf(v.x, -30.0f), 30.0f));
        o.y = __expf(fminf(fmaxf(v.y, -30.0f), 30.0f));
        o.z = __expf(fminf(fmaxf(v.z, -30.0f), 30.0f));
        o.w = __expf(fminf(fmaxf(v.w, -30.0f), 30.0f));
        ((float4*)g_xexp)[i] = o;
    }
}

__global__ void k_zero() {
    int i = blockIdx.x * blockDim.x + threadIdx.x;
    uint2 z = make_uint2(0u, 0u);
    if (i < DEN_SLICES * DEN_CAP * 32) g_den_sell[i] = z;
    if (i < BB * NUM_SLICES * NUM_CAP * 32) g_num_sell[i] = z;
    if (i < S_DEN) g_den_cnt[i] = 0;
    if (i < BB * S_NUM) g_num_cnt[i] = 0;
}

// direct SELL scatter: slot j within row from atomic cursor; pads stay zero
__global__ void k_scatter(const int* __restrict__ den_in, const int* __restrict__ den_out,
                          const int* __restrict__ den_pdf, const float* __restrict__ den_prob,
                          const int* __restrict__ num_in, const int* __restrict__ num_out,
                          const int* __restrict__ num_pdf, const float* __restrict__ num_prob) {
    int i = blockIdx.x * blockDim.x + threadIdx.x;
    if (i < E_DEN) {
        int o = den_out[i];
        int j = atomicAdd(&g_den_cnt[o], 1);
        if (j < DEN_CAP) {
            int slice = o >> 5, lane = o & 31;
            g_den_sell[slice * (DEN_CAP * 32) + j * 32 + lane] =
                make_uint2((unsigned)den_in[i] | ((unsigned)den_pdf[i] << 16),
                           __float_as_uint(den_prob[i]));
        }
    }
    if (i < BB * E_NUM) {
        int b = i / E_NUM;
        int o = num_out[i];
        int j = atomicAdd(&g_num_cnt[b * S_NUM + o], 1);
        if (j < NUM_CAP) {
            int slice = o >> 5, lane = o & 31;
            g_num_sell[(b * NUM_SLICES + slice) * (NUM_CAP * 32) + j * 32 + lane] =
                make_uint2((unsigned)num_in[i] | ((unsigned)num_pdf[i] << 16),
                           __float_as_uint(num_prob[i]));
        }
    }
}

// per-slice max row length (single block, 1024 threads)
__global__ void k_slicelen() {
    int tid = threadIdx.x;
    if (tid < DEN_SLICES) {
        int m = 0;
        for (int r = 0; r < 32; r++) {
            int s = tid * 32 + r;
            if (s < S_DEN) m = max(m, g_den_cnt[s]);
        }
        g_den_slen[tid] = min(m, DEN_CAP);
    }
    int idx = tid - 64;
    if (idx >= 0 && idx < BB * NUM_SLICES) {
        int m = 0;
        for (int r = 0; r < 32; r++)
            m = max(m, g_num_cnt[(idx >> 4) * S_NUM + (idx & 15) * 32 + r]);
        g_num_slen[idx] = min(m, NUM_CAP);
    }
}

// ---------------------------------------------------------------------------
// Main recursion. grid = 128 CTAs, cluster 2. pair = blockIdx/2:
// pairs 0..31 den batches, 32..63 num batches. One SELL slice per warp; lane
// holds its state's register accumulator; one warp_sum per warp per frame.
// Halves exchanged raw via DSMEM; ONE cluster.sync per frame.
// ---------------------------------------------------------------------------
__global__ void __cluster_dims__(2, 1, 1) __launch_bounds__(1024, 1)
k_main(const int* __restrict__ xlen,
       const float* __restrict__ den_leaky, const float* __restrict__ den_final,
       const float* __restrict__ num_leaky, const float* __restrict__ num_final,
       int Tdim) {
    __shared__ float xs[DD];                              //  8192 B
    __shared__ float alpha[S_DEN];                        //  8000 B (local only)
    __shared__ __align__(16) float anewbuf[2 * S_DEN];    // 16000 B (parity dbl buf)
    __shared__ float clk[S_DEN];                          //  8000 B (coeff * leaky)
    __shared__ float red[32];
    __shared__ __align__(8) float hsum_own[2];
    __shared__ __align__(8) float hsum_peer[2];

    cg::cluster_group cluster = cg::this_cluster();
    int rank = (int)cluster.block_rank();
    int peer = rank ^ 1;

    int bid = blockIdx.x;
    int pair = bid >> 1;
    int b = pair & 31;
    bool isDen = pair < 32;

    int S = isDen ? S_DEN : S_NUM;
    float coeff = isDen ? DEN_LEAKY : NUM_LEAKY;
    const float* leaky = isDen ? den_leaky : (num_leaky + b * S_NUM);
    const float* finalp = isDen ? den_final : (num_final + b * S_NUM);

    // slice split between the two CTAs (slice-aligned state split)
    int nsl      = isDen ? (rank ? 32 : 31) : 8;          // slices owned
    int first    = isDen ? (rank ? 31 : 0)  : (rank ? 8 : 0);
    int my_first = isDen ? (rank ? 992 : 0) : (rank ? 256 : 0);  // first state
    int my_cnt   = isDen ? (rank ? 1008 : 992) : 256;            // states owned

    int tid = threadIdx.x;
    int wid = tid >> 5;
    int lane = tid & 31;

    for (int s = tid; s < S; s += 1024) {
        float cl = coeff * leaky[s];
        clk[s] = cl;
        alpha[s] = cl + (s == 0 ? 1.0f : 0.0f);
    }

    // per-warp slice setup (loop-invariant across frames)
    int sidx = first + wid;
    int mlen = 0;
    const uint2* sp = g_den_sell;
    if (wid < nsl) {
        if (isDen) {
            mlen = g_den_slen[sidx];
            sp = g_den_sell + sidx * (DEN_CAP * 32);
        } else {
            mlen = g_num_slen[b * NUM_SLICES + sidx];
            sp = g_num_sell + (b * NUM_SLICES + sidx) * (NUM_CAP * 32);
        }
    }
    int mystate = (sidx << 5) + lane;
    bool wr = (wid < nsl) && (mystate < S);

    int Tb = xlen[b];
    const float* xb = g_xexp + (size_t)b * Tdim * DD;
    double logz = 0.0;

    // hoisted peer DSMEM pointers (map once, reuse every frame)
    uint64_t* peer_anew[2];
    float* peer_hsum_p;
    peer_anew[0] = (uint64_t*)cluster.map_shared_rank(anewbuf + my_first, peer);
    peer_anew[1] = (uint64_t*)cluster.map_shared_rank(anewbuf + S_DEN + my_first, peer);
    peer_hsum_p  = cluster.map_shared_rank(hsum_peer, peer);

    // preload frame 0 into registers
    float r0 = xb[tid], r1 = xb[tid + 1024];

    for (int t = 0; t < Tb; t++) {
        int par = t & 1;
        float* anew = anewbuf + par * S_DEN;

        // stage x row (prefetched previous iteration); this barrier also orders
        // init/renorm alpha writes before this frame's gathers
        xs[tid] = r0;
        xs[tid + 1024] = r1;
        __syncthreads();
        if (t + 1 < Tb) {
            const float* nx = xb + (size_t)(t + 1) * DD;
            r0 = nx[tid];
            r1 = nx[tid + 1024];
        }

        // phase 2: SELL slice per warp — lane accumulates its state's row.
        // Coalesced LDG, independent iterations (good MLP), zero shfls here.
        float acc = 0.0f;
        #pragma unroll 4
        for (int j = 0; j < mlen; j++) {
            uint2 ed = __ldg(&sp[(j << 5) + lane]);
            acc += alpha[ed.x & 0xFFFFu] * __uint_as_float(ed.y) * xs[ed.x >> 16];
        }
        float wsum = warp_sum(acc);      // pads & out-of-range lanes add 0
        if (wr) anew[mystate] = acc;     // coalesced STS
        if (lane == 0) red[wid] = wsum;  // idle warps write 0
        __syncthreads();                 // anew own-half + red[] complete

        // half-sum: reduce + push to peer
        if (wid == 0) {
            float h = warp_sum(red[lane]);
            if (lane == 0) {
                hsum_own[par] = h;
                peer_hsum_p[par] = h;
            }
        }

        // push raw own half to peer's anew (packed 8B; 16B-aligned offsets)
        {
            const uint64_t* src = (const uint64_t*)(anew + my_first);
            uint64_t* dst = peer_anew[par];
            int n2 = my_cnt >> 1;
            for (int i = tid; i < n2; i += 1024)
                dst[i] = src[i];
        }

        cluster.sync();  // single barrier: peer half + half-sum visible

        float asum = hsum_own[par] + hsum_peer[par];
        float inv = 1.0f / asum;

        // renorm + leaky over FULL state vector, locally
        for (int i = tid; i < S; i += 1024)
            alpha[i] = anew[i] * inv + clk[i];
        if (tid == 0) logz += (double)logf(asum);
        // next frame's post-staging __syncthreads orders these alpha writes
        // against the next gathers.
    }

    // final-state weighting (alpha fully local in both ranks; rank 0 reports)
    __syncthreads();
    if (rank == 0) {
        float p = 0.0f;
        for (int i = tid; i < S; i += 1024) p += alpha[i] * finalp[i];
        p = warp_sum(p);
        if (lane == 0) red[wid] = p;
        __syncthreads();
        if (wid == 0) {
            float v = warp_sum(red[lane]);
            if (lane == 0) g_partial[pair] = logz + (double)logf(v);
        }
    }
    cluster.sync();  // peer must not exit while pushes may be in flight
}

__global__ void k_final(const int* __restrict__ xlen, float* __restrict__ out) {
    int lane = threadIdx.x;  // 32 threads
    double dden = g_partial[lane];
    double dnum = g_partial[32 + lane];
    long long len = (long long)xlen[lane];
    for (int d = 16; d; d >>= 1) {
        dden += __shfl_xor_sync(0xFFFFFFFFu, dden, d);
        dnum += __shfl_xor_sync(0xFFFFFFFFu, dnum, d);
        len  += __shfl_xor_sync(0xFFFFFFFFu, len, d);
    }
    if (lane == 0) out[0] = (float)(-(dnum - dden) / (double)len);
}

// ---------------------------------------------------------------------------
extern "C" void kernel_launch(void* const* d_in, const int* in_sizes, int n_in,
                              void* d_out, int out_size) {
    const float* x         = (const float*)d_in[0];
    const int*   xlen      = (const int*)d_in[1];
    const int*   den_e_in  = (const int*)d_in[2];
    const int*   den_e_out = (const int*)d_in[3];
    const int*   den_e_pdf = (const int*)d_in[4];
    const float* den_e_prob= (const float*)d_in[5];
    const float* den_leaky = (const float*)d_in[6];
    const float* den_final = (const float*)d_in[7];
    const int*   num_e_in  = (const int*)d_in[8];
    const int*   num_e_out = (const int*)d_in[9];
    const int*   num_e_pdf = (const int*)d_in[10];
    const float* num_e_prob= (const float*)d_in[11];
    const float* num_leaky = (const float*)d_in[12];
    const float* num_final = (const float*)d_in[13];
    float* out = (float*)d_out;

    int Tdim = in_sizes[0] / (BB * DD);  // x = [B, T, D]
    int n4 = in_sizes[0] / 4;

    k_exp<<<(n4 + 255) / 256, 256>>>(x, n4);

    int zn = BB * NUM_SLICES * NUM_CAP * 32;  // largest array to zero
    k_zero<<<(zn + 255) / 256, 256>>>();

    int hn = E_DEN > BB * E_NUM ? E_DEN : BB * E_NUM;
    k_scatter<<<(hn + 255) / 256, 256>>>(den_e_in, den_e_out, den_e_pdf, den_e_prob,
                                         num_e_in, num_e_out, num_e_pdf, num_e_prob);

    k_slicelen<<<1, 1024>>>();

    k_main<<<4 * BB, 1024>>>(xlen, den_leaky, den_final, num_leaky, num_final, Tdim);

    k_final<<<1, 32>>>(xlen, out);
}

// round 16
// speedup vs baseline: 3.1386x; 1.2693x over previous
#include <cuda_runtime.h>
#include <cuda_bf16.h>
#include <cooperative_groups.h>
#include <math.h>
#include <stdint.h>

namespace cg = cooperative_groups;

// ---------------------------------------------------------------------------
// ChainLoss (pychain leaky-HMM forward objective), den + num graphs.
//   - xexp precomputed once.
//   - den edges: SELL-32 in SLOT space — states counting-sorted by row length
//     (descending) into slots; slices get near-uniform row lengths (mlen ~=
//     mean, not max). Edge 'in' field pre-translated to slot at scatter.
//   - k_main: cluster-3 per den batch (63 slices = 3 x 21, stride-3 interleave
//     across ranks for balance); lane-serial SELL accumulation (zero per-state
//     shfls), raw thirds + partial sums exchanged via DSMEM (parity double
//     buffer), ONE cluster.sync per frame, local renorm of the full vector.
//   - num batches: solo CTAs (gather work is tiny), no cluster ops.
// ---------------------------------------------------------------------------

#define BB     32
#define DD     2048
#define S_DEN  2000
#define E_DEN  60000
#define S_NUM  512
#define E_NUM  2048

#define DEN_SLICES 63      // 2016 slots / 32
#define DEN_SLOTS  2016
#define DEN_CAP    96
#define DEN_NSL    21      // slices per rank (63 / 3)
#define NUM_SLICES 16      // per batch
#define NUM_CAP    32

#define DEN_LEAKY 1e-5f
#define NUM_LEAKY 1e-20f

// -------- static scratch (no allocations allowed) --------
__device__ float g_xexp[(size_t)BB * 400 * DD];               // ~100 MB

__device__ uint2 g_den_sell[DEN_SLICES * DEN_CAP * 32];       // 1.5 MB
__device__ int   g_den_cnt[S_DEN];
__device__ int   g_den_cur[S_DEN];
__device__ int   g_den_perm[S_DEN];    // slot -> state
__device__ int   g_den_islot[S_DEN];   // state -> slot
__device__ int   g_den_slen[DEN_SLICES];

__device__ uint2 g_num_sell[BB * NUM_SLICES * NUM_CAP * 32];  // 4.2 MB
__device__ int   g_num_cnt[BB * S_NUM];
__device__ int   g_num_slen[BB * NUM_SLICES];

__device__ double g_partial[2 * BB];

// ---------------------------------------------------------------------------
__device__ __forceinline__ float warp_sum(float v) {
    v += __shfl_xor_sync(0xFFFFFFFFu, v, 16);
    v += __shfl_xor_sync(0xFFFFFFFFu, v, 8);
    v += __shfl_xor_sync(0xFFFFFFFFu, v, 4);
    v += __shfl_xor_sync(0xFFFFFFFFu, v, 2);
    v += __shfl_xor_sync(0xFFFFFFFFu, v, 1);
    return v;
}

// ---------------------------------------------------------------------------
__global__ void k_exp(const float* __restrict__ x, int n4) {
    int i = blockIdx.x * blockDim.x + threadIdx.x;
    if (i < n4) {
        float4 v = ((const float4*)x)[i];
        float4 o;
        o.x = __expf(fminf(fmaxf(v.x, -30.0f), 30.0f));
        o.y = __expf(fminf(fmaxf(v.y, -30.0f), 30.0f));
        o.z = __expf(fminf(fmaxf(v.z, -30.0f), 30.0f));
        o.w = __expf(fminf(fmaxf(v.w, -30.0f), 30.0f));
        ((float4*)g_xexp)[i] = o;
    }
}

__global__ void k_zero() {
    int i = blockIdx.x * blockDim.x + threadIdx.x;
    uint2 z = make_uint2(0u, 0u);
    if (i < DEN_SLICES * DEN_CAP * 32) g_den_sell[i] = z;
    if (i < BB * NUM_SLICES * NUM_CAP * 32) g_num_sell[i] = z;
    if (i < S_DEN) { g_den_cnt[i] = 0; g_den_cur[i] = 0; }
    if (i < BB * S_NUM) g_num_cnt[i] = 0;
    if (i < DEN_SLICES) g_den_slen[i] = 0;
    if (i < BB * NUM_SLICES) g_num_slen[i] = 0;
}

__global__ void k_count(const int* __restrict__ den_out) {
    int i = blockIdx.x * blockDim.x + threadIdx.x;
    if (i < E_DEN) atomicAdd(&g_den_cnt[den_out[i]], 1);
}

// counting sort of den states by row length (descending) -> slot permutation
__global__ void k_perm() {
    __shared__ int hist[DEN_CAP + 1], base[DEN_CAP + 1], off[DEN_CAP + 1];
    int tid = threadIdx.x;  // 1024
    if (tid <= DEN_CAP) { hist[tid] = 0; off[tid] = 0; }
    __syncthreads();
    for (int s = tid; s < S_DEN; s += 1024)
        atomicAdd(&hist[min(g_den_cnt[s], DEN_CAP)], 1);
    __syncthreads();
    if (tid == 0) {                     // descending: base[c] = sum_{c'>c} hist
        int acc = 0;
        for (int c = DEN_CAP; c >= 0; c--) { base[c] = acc; acc += hist[c]; }
    }
    __syncthreads();
    for (int s = tid; s < S_DEN; s += 1024) {
        int c = min(g_den_cnt[s], DEN_CAP);
        int slot = base[c] + atomicAdd(&off[c], 1);
        g_den_perm[slot] = s;
        g_den_islot[s] = slot;
    }
}

// SELL scatter. den: in-field pre-translated to SLOT space; placed by islot.
__global__ void k_scatter(const int* __restrict__ den_in, const int* __restrict__ den_out,
                          const int* __restrict__ den_pdf, const float* __restrict__ den_prob,
                          const int* __restrict__ num_in, const int* __restrict__ num_out,
                          const int* __restrict__ num_pdf, const float* __restrict__ num_prob) {
    int i = blockIdx.x * blockDim.x + threadIdx.x;
    if (i < E_DEN) {
        int o = den_out[i];
        int j = atomicAdd(&g_den_cur[o], 1);
        if (j < DEN_CAP) {
            int slot = g_den_islot[o];
            int slice = slot >> 5, lane = slot & 31;
            unsigned in_slot = (unsigned)g_den_islot[den_in[i]];
            g_den_sell[slice * (DEN_CAP * 32) + j * 32 + lane] =
                make_uint2(in_slot | ((unsigned)den_pdf[i] << 16),
                           __float_as_uint(den_prob[i]));
        }
    }
    if (i < BB * E_NUM) {
        int b = i / E_NUM;
        int o = num_out[i];
        int j = atomicAdd(&g_num_cnt[b * S_NUM + o], 1);
        if (j < NUM_CAP) {
            int slice = o >> 5, lane = o & 31;
            g_num_sell[(b * NUM_SLICES + slice) * (NUM_CAP * 32) + j * 32 + lane] =
                make_uint2((unsigned)num_in[i] | ((unsigned)num_pdf[i] << 16),
                           __float_as_uint(num_prob[i]));
        }
    }
}

// parallel per-slice max row length via atomicMax
__global__ void k_slicelen() {
    int i = blockIdx.x * blockDim.x + threadIdx.x;
    if (i < S_DEN)
        atomicMax(&g_den_slen[g_den_islot[i] >> 5], min(g_den_cnt[i], DEN_CAP));
    if (i < BB * S_NUM) {
        int b = i >> 9, s = i & 511;
        atomicMax(&g_num_slen[b * NUM_SLICES + (s >> 5)], min(g_num_cnt[i], NUM_CAP));
    }
}

// ---------------------------------------------------------------------------
// Main recursion. grid = 129 CTAs, cluster 3.
//   bid < 96 : den, batch = bid/3, rank = bid%3, slices rank,rank+3,... (21).
//   bid >= 96: num, solo CTA, batch = bid-96 (CTA 128 idle).
// ---------------------------------------------------------------------------
__global__ void __cluster_dims__(3, 1, 1) __launch_bounds__(1024, 1)
k_main(const int* __restrict__ xlen,
       const float* __restrict__ den_leaky, const float* __restrict__ den_final,
       const float* __restrict__ num_leaky, const float* __restrict__ num_final,
       int Tdim) {
    __shared__ float xs[DD];                                 //  8192 B
    __shared__ float alpha[S_DEN];                           //  8000 B (slot space)
    __shared__ __align__(16) float anewbuf[2 * DEN_SLOTS];   // 16128 B (parity dbl)
    __shared__ float clk[S_DEN];                             //  8000 B
    __shared__ float red[32];
    __shared__ __align__(8) float hsum_all[2][4];

    int bid = blockIdx.x;
    int tid = threadIdx.x;
    int wid = tid >> 5;
    int lane = tid & 31;

    if (bid < 96) {
        // ================= DEN: cluster-3, slot space =================
        cg::cluster_group cluster = cg::this_cluster();
        int rank = (int)cluster.block_rank();
        int b = bid / 3;
        int p1 = (rank + 1) % 3, p2 = (rank + 2) % 3;

        // init alpha/clk in slot space (perm gather once)
        for (int slot = tid; slot < S_DEN; slot += 1024) {
            int st = g_den_perm[slot];
            float cl = DEN_LEAKY * den_leaky[st];
            clk[slot] = cl;
            alpha[slot] = cl + (st == 0 ? 1.0f : 0.0f);
        }

        // per-warp slice setup: sidx = rank + 3*wid (stride-3 interleave)
        int sidx = rank + 3 * wid;
        int mlen = 0;
        const uint2* sp = g_den_sell;
        bool busy = (wid < DEN_NSL);
        if (busy) {
            mlen = g_den_slen[sidx];
            sp = g_den_sell + sidx * (DEN_CAP * 32);
        }
        int myslot = (sidx << 5) + lane;

        int Tb = xlen[b];
        const float* xb = g_xexp + (size_t)b * Tdim * DD;
        double logz = 0.0;

        // hoisted peer DSMEM base pointers
        uint64_t* pa[2][2];
        float* ph[2][2];
        for (int par = 0; par < 2; par++) {
            pa[par][0] = (uint64_t*)cluster.map_shared_rank(anewbuf + par * DEN_SLOTS, p1);
            pa[par][1] = (uint64_t*)cluster.map_shared_rank(anewbuf + par * DEN_SLOTS, p2);
            ph[par][0] = (float*)cluster.map_shared_rank(&hsum_all[par][rank], p1);
            ph[par][1] = (float*)cluster.map_shared_rank(&hsum_all[par][rank], p2);
        }

        float r0 = xb[tid], r1 = xb[tid + 1024];

        for (int t = 0; t < Tb; t++) {
            int par = t & 1;
            float* anew = anewbuf + par * DEN_SLOTS;

            xs[tid] = r0;
            xs[tid + 1024] = r1;
            __syncthreads();
            if (t + 1 < Tb) {
                const float* nx = xb + (size_t)(t + 1) * DD;
                r0 = nx[tid];
                r1 = nx[tid + 1024];
            }

            // SELL slice per warp, slot space; zero-pads contribute 0
            float acc = 0.0f;
            #pragma unroll 4
            for (int j = 0; j < mlen; j++) {
                uint2 ed = __ldg(&sp[(j << 5) + lane]);
                acc += alpha[ed.x & 0xFFFFu] * __uint_as_float(ed.y) * xs[ed.x >> 16];
            }
            float wsum = warp_sum(acc);
            if (busy) anew[myslot] = acc;     // coalesced; phantom slots get 0
            if (lane == 0) red[wid] = wsum;
            __syncthreads();

            if (wid == 0) {
                float h = warp_sum(red[lane]);
                if (lane == 0) {
                    hsum_all[par][rank] = h;
                    *ph[par][0] = h;
                    *ph[par][1] = h;
                }
            }

            // push own 21 slices (336 u64) to both peers
            {
                const uint64_t* src = (const uint64_t*)anew;
                uint64_t* d1 = pa[par][0];
                uint64_t* d2 = pa[par][1];
                if (tid < DEN_NSL * 16) {
                    int slice = rank + 3 * (tid >> 4);
                    int idx = (slice << 4) + (tid & 15);
                    uint64_t v = src[idx];
                    d1[idx] = v;
                    d2[idx] = v;
                }
            }

            cluster.sync();

            float asum = hsum_all[par][0] + hsum_all[par][1] + hsum_all[par][2];
            float inv = 1.0f / asum;
            for (int i = tid; i < S_DEN; i += 1024)
                alpha[i] = anew[i] * inv + clk[i];
            if (tid == 0) logz += (double)logf(asum);
        }

        __syncthreads();
        if (rank == 0) {
            float p = 0.0f;
            for (int i = tid; i < S_DEN; i += 1024)
                p += alpha[i] * __ldg(&den_final[g_den_perm[i]]);
            p = warp_sum(p);
            if (lane == 0) red[wid] = p;
            __syncthreads();
            if (wid == 0) {
                float v = warp_sum(red[lane]);
                if (lane == 0) g_partial[b] = logz + (double)logf(v);
            }
        }
        cluster.sync();
    } else {
        // ================= NUM: solo CTA, state space =================
        int nb = bid - 96;
        if (nb >= BB) return;   // idle CTA (no cluster ops anywhere here)

        const float* leaky = num_leaky + nb * S_NUM;
        const float* finalp = num_final + nb * S_NUM;

        for (int s = tid; s < S_NUM; s += 1024) {
            float cl = NUM_LEAKY * leaky[s];
            clk[s] = cl;
            alpha[s] = cl + (s == 0 ? 1.0f : 0.0f);
        }

        int mlen = 0;
        const uint2* sp = g_num_sell;
        bool busy = (wid < NUM_SLICES);
        if (busy) {
            mlen = g_num_slen[nb * NUM_SLICES + wid];
            sp = g_num_sell + (nb * NUM_SLICES + wid) * (NUM_CAP * 32);
        }
        int mystate = (wid << 5) + lane;

        int Tb = xlen[nb];
        const float* xb = g_xexp + (size_t)nb * Tdim * DD;
        double logz = 0.0;
        float* anew = anewbuf;   // no peer traffic -> single buffer

        float r0 = xb[tid], r1 = xb[tid + 1024];

        for (int t = 0; t < Tb; t++) {
            xs[tid] = r0;
            xs[tid + 1024] = r1;
            __syncthreads();
            if (t + 1 < Tb) {
                const float* nx = xb + (size_t)(t + 1) * DD;
                r0 = nx[tid];
                r1 = nx[tid + 1024];
            }

            float acc = 0.0f;
            #pragma unroll 4
            for (int j = 0; j < mlen; j++) {
                uint2 ed = __ldg(&sp[(j << 5) + lane]);
                acc += alpha[ed.x & 0xFFFFu] * __uint_as_float(ed.y) * xs[ed.x >> 16];
            }
            float wsum = warp_sum(acc);
            if (busy) anew[mystate] = acc;
            if (lane == 0) red[wid] = wsum;
            __syncthreads();

            if (wid == 0) {
                float h = warp_sum(red[lane]);
                if (lane == 0) hsum_all[0][0] = h;
            }
            __syncthreads();

            float asum = hsum_all[0][0];
            float inv = 1.0f / asum;
            for (int i = tid; i < S_NUM; i += 1024)
                alpha[i] = anew[i] * inv + clk[i];
            if (tid == 0) logz += (double)logf(asum);
            __syncthreads();   // alpha ready before next gathers
        }

        float p = 0.0f;
        for (int i = tid; i < S_NUM; i += 1024) p += alpha[i] * finalp[i];
        p = warp_sum(p);
        if (lane == 0) red[wid] = p;
        __syncthreads();
        if (wid == 0) {
            float v = warp_sum(red[lane]);
            if (lane == 0) g_partial[32 + nb] = logz + (double)logf(v);
        }
    }
}

__global__ void k_final(const int* __restrict__ xlen, float* __restrict__ out) {
    int lane = threadIdx.x;  // 32 threads
    double dden = g_partial[lane];
    double dnum = g_partial[32 + lane];
    long long len = (long long)xlen[lane];
    for (int d = 16; d; d >>= 1) {
        dden += __shfl_xor_sync(0xFFFFFFFFu, dden, d);
        dnum += __shfl_xor_sync(0xFFFFFFFFu, dnum, d);
        len  += __shfl_xor_sync(0xFFFFFFFFu, len, d);
    }
    if (lane == 0) out[0] = (float)(-(dnum - dden) / (double)len);
}

// ---------------------------------------------------------------------------
extern "C" void kernel_launch(void* const* d_in, const int* in_sizes, int n_in,
                              void* d_out, int out_size) {
    const float* x         = (const float*)d_in[0];
    const int*   xlen      = (const int*)d_in[1];
    const int*   den_e_in  = (const int*)d_in[2];
    const int*   den_e_out = (const int*)d_in[3];
    const int*   den_e_pdf = (const int*)d_in[4];
    const float* den_e_prob= (const float*)d_in[5];
    const float* den_leaky = (const float*)d_in[6];
    const float* den_final = (const float*)d_in[7];
    const int*   num_e_in  = (const int*)d_in[8];
    const int*   num_e_out = (const int*)d_in[9];
    const int*   num_e_pdf = (const int*)d_in[10];
    const float* num_e_prob= (const float*)d_in[11];
    const float* num_leaky = (const float*)d_in[12];
    const float* num_final = (const float*)d_in[13];
    float* out = (float*)d_out;

    int Tdim = in_sizes[0] / (BB * DD);  // x = [B, T, D]
    int n4 = in_sizes[0] / 4;

    k_exp<<<(n4 + 255) / 256, 256>>>(x, n4);

    int zn = BB * NUM_SLICES * NUM_CAP * 32;   // largest array to zero
    k_zero<<<(zn + 255) / 256, 256>>>();

    k_count<<<(E_DEN + 255) / 256, 256>>>(den_e_out);
    k_perm<<<1, 1024>>>();

    int hn = E_DEN > BB * E_NUM ? E_DEN : BB * E_NUM;
    k_scatter<<<(hn + 255) / 256, 256>>>(den_e_in, den_e_out, den_e_pdf, den_e_prob,
                                         num_e_in, num_e_out, num_e_pdf, num_e_prob);

    k_slicelen<<<(BB * S_NUM + 255) / 256, 256>>>();

    k_main<<<129, 1024>>>(xlen, den_leaky, den_final, num_leaky, num_final, Tdim);

    k_final<<<1, 32>>>(xlen, out);
}